// round 16
// baseline (speedup 1.0000x reference)
#include <cuda_runtime.h>
#include <cstdint>

typedef unsigned long long u64;
typedef unsigned int u32;
typedef unsigned short u16;
#define DEV __device__ __forceinline__

// ---------------- global scratch: tf32 weight planes, fragment-pair-major [K/8][N][8] ----------------
// within each 8-k group, order (k0,k4),(k1,k5),(k2,k6),(k3,k7) so lane q LDG.64 -> (b0,b1)
__device__ __align__(256) u32 g_w1[512 * 256];
__device__ __align__(256) u32 g_w2[256 * 256];
__device__ __align__(256) u32 g_w3[256 * 128];

// ================= PTX helpers =================
DEV u32 f2tf(float v) { u32 r; asm("cvt.rna.tf32.f32 %0, %1;" : "=r"(r) : "f"(v)); return r; }

DEV void mma16808(float* d, u32 a0, u32 a1, u32 a2, u32 a3, u32 b0, u32 b1) {
    asm volatile(
        "mma.sync.aligned.m16n8k8.row.col.f32.tf32.tf32.f32 "
        "{%0,%1,%2,%3}, {%4,%5,%6,%7}, {%8,%9}, {%0,%1,%2,%3};"
        : "+f"(d[0]), "+f"(d[1]), "+f"(d[2]), "+f"(d[3])
        : "r"(a0), "r"(a1), "r"(a2), "r"(a3), "r"(b0), "r"(b1));
}

// position of k (0..7) within the pair-packed group
DEV int kpos8(int k) { return ((k & 3) << 1) | ((k >> 2) & 1); }

// ================= weight tf32-convert + fragment-pack pre-kernel =================
__global__ void conv_w(const float* __restrict__ W1, const float* __restrict__ W2,
                       const float* __restrict__ W3)
{
    int idx = blockIdx.x * blockDim.x + threadIdx.x;
    int stride = gridDim.x * blockDim.x;
    for (int i = idx; i < 512 * 256; i += stride) {
        int k = i >> 8, n = i & 255;
        g_w1[(((k >> 3) * 256 + n) << 3) + kpos8(k & 7)] = f2tf(W1[i]);
    }
    for (int i = idx; i < 256 * 256; i += stride) {
        int k = i >> 8, n = i & 255;
        g_w2[(((k >> 3) * 256 + n) << 3) + kpos8(k & 7)] = f2tf(W2[i]);
    }
    for (int i = idx; i < 256 * 128; i += stride) {
        int k = i >> 7, n = i & 127;
        g_w3[(((k >> 3) * 128 + n) << 3) + kpos8(k & 7)] = f2tf(W3[i]);
    }
}

// ================= geometry =================
constexpr int BATCH = 16384;
constexpr int BT    = 8;
constexpr int MT    = 96;
constexpr int THREADS = 512;

constexpr int AFSTR = 260;   // A plane row stride (u32 words); 260 % 32 == 4 -> conflict-free LDS.64
constexpr int ASSTR = 36;    // layer-1 A slice row stride (32 k + pad); 36 % 32 == 4

// smem layout (bytes)
constexpr int A_OFF  = 0;                        // 96*260*4 = 99840 (tf32 activations, PAIR-PERMUTED k)
constexpr int AS_SZ  = MT * ASSTR * 4;           // 13824; layer-1 slices alias A region
constexpr int HC_OFF = 99840;                    // fp32 scratch 96*264*4 = 101376
constexpr int HCSTR  = 264;                      // conflict-free D-store / mix reads
constexpr int AM_OFF = 201216;                   // 144 floats
constexpr int SMEM_BYTES = 201856;

// Fixed ECG graph neighbor lists (incl. self), 42 nonzeros of the 12x12 A_norm.
__device__ constexpr int NBR_OFF[13] = {0,5,11,16,20,23,26,28,31,34,37,40,42};
__device__ constexpr int NBR[42] = {
    0,1,2,3,4,
    0,1,2,3,4,5,
    0,1,2,3,5,
    0,1,2,3,
    0,1,4,
    1,2,5,
    6,7,
    6,7,8,
    7,8,9,
    8,9,10,
    9,10,11,
    10,11
};

// One 8-k step of the tf32 GEMM. A is PAIR-PERMUTED: word (g*8 + 2q) holds k=q,
// word (g*8 + 2q + 1) holds k=q+4 -> one LDS.64 yields (a0, a2) / (a1, a3).
// B: fragment-pair GLOBAL plane, bp pre-offset to (kc*N + cb + lr)*8 + 2q.
template<int NT>
DEV void gemm_kstep(const u32* A, int astr, int kcol, int rb,
                    const u32* bp, float acc[3][NT][4], int lane)
{
    u64 bv[NT];
    #pragma unroll
    for (int nt = 0; nt < NT; nt++)
        bv[nt] = *(const u64*)(bp + (nt << 6));
    const int lr = lane >> 2;
    const int q2 = (lane & 3) << 1;
    #pragma unroll
    for (int mt = 0; mt < 3; mt++) {
        int r = rb + mt * 16 + lr;
        u64 av0 = *(const u64*)(A + r * astr + kcol + q2);        // (a0, a2)
        u64 av1 = *(const u64*)(A + (r + 8) * astr + kcol + q2);  // (a1, a3)
        u32 a0 = (u32)av0, a2 = (u32)(av0 >> 32);
        u32 a1 = (u32)av1, a3 = (u32)(av1 >> 32);
        #pragma unroll
        for (int nt = 0; nt < NT; nt++)
            mma16808(acc[mt][nt], a0, a1, a2, a3, (u32)bv[nt], (u32)(bv[nt] >> 32));
    }
}

// Single-pass readback: all warps dump D into Hc, one sync, then all threads mix
// (A-mix + bias(+relu)) and write next-layer tf32 A plane (pair-permuted),
// or fused mean/max epilogue.
template<int NT, bool FINAL>
DEV void readback(unsigned char* smem, float acc[3][NT][4],
                  const float* Am, const float* __restrict__ bias,
                  float* __restrict__ out, long long obase,
                  int tid, int lane, int rg, int cbase)
{
    float* Hc = (float*)(smem + HC_OFF);
    u32* afp = (u32*)(smem + A_OFF);
    const int lr = lane >> 2, q = lane & 3;
    #pragma unroll
    for (int mt = 0; mt < 3; mt++) {
        int r = rg * 48 + mt * 16 + lr;
        #pragma unroll
        for (int nt = 0; nt < NT; nt++) {
            int c = cbase + nt * 8 + q * 2;
            *(float2*)(Hc + r * HCSTR + c) = make_float2(acc[mt][nt][0], acc[mt][nt][1]);
            *(float2*)(Hc + (r + 8) * HCSTR + c) = make_float2(acc[mt][nt][2], acc[mt][nt][3]);
        }
    }
    __syncthreads();
    if (!FINAL) {
        #pragma unroll
        for (int s = 0; s < 4; s++) {
            int col = tid & 255;
            int b   = (tid >> 8) + 2 * s;
            int pcol = (col & ~7) | kpos8(col & 7);   // pair-permuted write position
            float h[12];
            #pragma unroll
            for (int l = 0; l < 12; l++) h[l] = Hc[(b * 12 + l) * HCSTR + col];
            float bv = __ldg(bias + col);
            #pragma unroll
            for (int l = 0; l < 12; l++) {
                float a = 0.f;
                #pragma unroll
                for (int qq = NBR_OFF[l]; qq < NBR_OFF[l + 1]; qq++)
                    a += Am[l * 12 + NBR[qq]] * h[NBR[qq]];
                float y = fmaxf(a + bv, 0.f);
                afp[(b * 12 + l) * AFSTR + pcol] = f2tf(y);
            }
        }
        __syncthreads();
    } else {
        #pragma unroll
        for (int s = 0; s < 2; s++) {
            int col = tid & 127;
            int b   = (tid >> 7) + 4 * s;
            float h[12];
            #pragma unroll
            for (int l = 0; l < 12; l++) h[l] = Hc[(b * 12 + l) * HCSTR + col];
            float bv = __ldg(bias + col);
            float sum = 0.f, mx = -3.402823466e38f;
            #pragma unroll
            for (int l = 0; l < 12; l++) {
                float a = 0.f;
                #pragma unroll
                for (int qq = NBR_OFF[l]; qq < NBR_OFF[l + 1]; qq++)
                    a += Am[l * 12 + NBR[qq]] * h[NBR[qq]];
                float y = a + bv;
                sum += y;
                mx = fmaxf(mx, y);
            }
            float* op = out + (obase + b) * 256;
            op[col]       = sum * (1.0f / 12.0f);
            op[128 + col] = mx;
        }
    }
}

__global__ void __launch_bounds__(THREADS, 1)
ecg_mma(const float* __restrict__ x,
        const float* __restrict__ b1, const float* __restrict__ b2,
        const float* __restrict__ b3, float* __restrict__ out)
{
    extern __shared__ unsigned char smem[];
    float* Am = (float*)(smem + AM_OFF);

    const int tid  = threadIdx.x;
    const int lane = tid & 31;
    const int w    = tid >> 5;       // 0..15
    const int rg   = w >> 3;         // 0..1 (M group)
    const int cg   = w & 7;          // 0..7 (N group)
    const int rb   = rg * 48;
    const int cb   = cg * 32;        // N=256 layers
    const int cb3  = cg * 16;        // N=128 layer
    const int lr   = lane >> 2;
    const int q    = lane & 3;
    const long long rowbase = (long long)blockIdx.x * MT;
    const long long obase   = (long long)blockIdx.x * BT;

    if (tid == 0) {
        float a[12][12];
        for (int i = 0; i < 12; i++)
            for (int j = 0; j < 12; j++) a[i][j] = (i == j) ? 2.0f : 0.0f;
        const int ei[15] = {0,0,1,0,1,2,0,1,1,2,6,7,8,9,10};
        const int ej[15] = {1,2,2,3,3,3,4,4,5,5,7,8,9,10,11};
        for (int e = 0; e < 15; e++) { a[ei[e]][ej[e]] = 1.0f; a[ej[e]][ei[e]] = 1.0f; }
        float dinv[12];
        for (int i = 0; i < 12; i++) {
            float s = 0.f;
            for (int j = 0; j < 12; j++) s += a[i][j];
            dinv[i] = 1.0f / sqrtf(s);
        }
        for (int i = 0; i < 12; i++)
            for (int j = 0; j < 12; j++)
                Am[i * 12 + j] = dinv[i] * a[i][j] * dinv[j];
    }

    // per-warp B fragment base offsets (u32 units): (cb + lr)*8 + 2q
    const u32* bp1 = g_w1 + ((cb  + lr) << 3) + (q << 1);
    const u32* bp2 = g_w2 + ((cb  + lr) << 3) + (q << 1);
    const u32* bp3 = g_w3 + ((cb3 + lr) << 3) + (q << 1);
    constexpr int KSTEP256 = 256 * 8;   // u32 per 8-k step, N=256
    constexpr int KSTEP128 = 128 * 8;   // N=128

    // layer-1 A staging: row xr (active <96), k-quarter xq (one 8-group each)
    const int xr = tid >> 2, xq = tid & 3;
    const bool xact = tid < MT * 4;

    u32* as_[2] = {(u32*)(smem + A_OFF), (u32*)(smem + A_OFF + AS_SZ)};

    float acc[3][4][4];
    #pragma unroll
    for (int i = 0; i < 3; i++)
        #pragma unroll
        for (int j = 0; j < 4; j++)
            #pragma unroll
            for (int v = 0; v < 4; v++) acc[i][j][v] = 0.f;

    // ---------------- Layer 1: X(96x512) @ W1 (K=512, 16 slices of 32 k) ----------------
    {
        if (xact) {
            float4 v0 = *(const float4*)(x + (rowbase + xr) * 512 + xq * 8);
            float4 v1 = *(const float4*)(x + (rowbase + xr) * 512 + xq * 8 + 4);
            u32* d = as_[0] + xr * ASSTR + xq * 8;
            // pair-permuted: even positions get k0..k3, odd positions get k4..k7
            *(uint4*)(d)     = make_uint4(f2tf(v0.x), f2tf(v1.x), f2tf(v0.y), f2tf(v1.y));
            *(uint4*)(d + 4) = make_uint4(f2tf(v0.z), f2tf(v1.z), f2tf(v0.w), f2tf(v1.w));
        }
        __syncthreads();

        for (int it = 0; it < 16; it++) {
            const int cur = it & 1, nxt = cur ^ 1;
            const bool more = it < 15;
            float4 v0, v1;
            if (more && xact) {
                v0 = *(const float4*)(x + (rowbase + xr) * 512 + (it + 1) * 32 + xq * 8);
                v1 = *(const float4*)(x + (rowbase + xr) * 512 + (it + 1) * 32 + xq * 8 + 4);
            }
            #pragma unroll
            for (int ks = 0; ks < 4; ks++)
                gemm_kstep<4>(as_[cur], ASSTR, ks * 8, rb,
                              bp1 + (it * 4 + ks) * KSTEP256, acc, lane);
            if (more && xact) {
                u32* d = as_[nxt] + xr * ASSTR + xq * 8;
                *(uint4*)(d)     = make_uint4(f2tf(v0.x), f2tf(v1.x), f2tf(v0.y), f2tf(v1.y));
                *(uint4*)(d + 4) = make_uint4(f2tf(v0.z), f2tf(v1.z), f2tf(v0.w), f2tf(v1.w));
            }
            __syncthreads();
        }
    }
    readback<4, false>(smem, acc, Am, b1, out, obase, tid, lane, rg, cb);

    // ---------------- Layer 2: H1(96x256) @ W2 (K=256, 32 ksteps, NO barriers) ----------------
    #pragma unroll
    for (int i = 0; i < 3; i++)
        #pragma unroll
        for (int j = 0; j < 4; j++)
            #pragma unroll
            for (int v = 0; v < 4; v++) acc[i][j][v] = 0.f;
    {
        const u32* afp = (const u32*)(smem + A_OFF);
        #pragma unroll 4
        for (int kc = 0; kc < 32; kc++)
            gemm_kstep<4>(afp, AFSTR, kc * 8, rb, bp2 + kc * KSTEP256, acc, lane);
    }
    readback<4, false>(smem, acc, Am, b2, out, obase, tid, lane, rg, cb);

    // ---------------- Layer 3: H2(96x256) @ W3 (K=256, 32 ksteps, N=128, NO barriers) ----------------
    float acc3[3][2][4];
    #pragma unroll
    for (int i = 0; i < 3; i++)
        #pragma unroll
        for (int j = 0; j < 2; j++)
            #pragma unroll
            for (int v = 0; v < 4; v++) acc3[i][j][v] = 0.f;
    {
        const u32* afp = (const u32*)(smem + A_OFF);
        #pragma unroll 4
        for (int kc = 0; kc < 32; kc++)
            gemm_kstep<2>(afp, AFSTR, kc * 8, rb, bp3 + kc * KSTEP128, acc3, lane);
    }
    readback<2, true>(smem, acc3, Am, b3, out, obase, tid, lane, rg, cb3);
}

extern "C" void kernel_launch(void* const* d_in, const int* in_sizes, int n_in,
                              void* d_out, int out_size)
{
    const float* x  = (const float*)d_in[0];
    const float* W1 = (const float*)d_in[1];
    const float* b1 = (const float*)d_in[2];
    const float* W2 = (const float*)d_in[3];
    const float* b2 = (const float*)d_in[4];
    const float* W3 = (const float*)d_in[5];
    const float* b3 = (const float*)d_in[6];
    float* out = (float*)d_out;

    conv_w<<<148, 512>>>(W1, W2, W3);

    cudaFuncSetAttribute(ecg_mma, cudaFuncAttributeMaxDynamicSharedMemorySize, SMEM_BYTES);
    ecg_mma<<<BATCH / BT, THREADS, SMEM_BYTES>>>(x, b1, b2, b3, out);
}

// round 17
// speedup vs baseline: 1.2088x; 1.2088x over previous
#include <cuda_runtime.h>
#include <cstdint>

typedef unsigned long long u64;
typedef unsigned int u32;
typedef unsigned short u16;
#define DEV __device__ __forceinline__

// ---------------- global scratch: tf32 weight planes, fragment-pair-major [K/8][N][8] ----------------
// within each 8-k group, order (k0,k4),(k1,k5),(k2,k6),(k3,k7) so lane q LDG.64 -> (b0,b1)
__device__ __align__(256) u32 g_w1[512 * 256];
__device__ __align__(256) u32 g_w2[256 * 256];
__device__ __align__(256) u32 g_w3[256 * 128];

// ================= PTX helpers =================
DEV u32 f2tf(float v) { u32 r; asm("cvt.rna.tf32.f32 %0, %1;" : "=r"(r) : "f"(v)); return r; }

DEV void mma16808(float* d, u32 a0, u32 a1, u32 a2, u32 a3, u32 b0, u32 b1) {
    asm volatile(
        "mma.sync.aligned.m16n8k8.row.col.f32.tf32.tf32.f32 "
        "{%0,%1,%2,%3}, {%4,%5,%6,%7}, {%8,%9}, {%0,%1,%2,%3};"
        : "+f"(d[0]), "+f"(d[1]), "+f"(d[2]), "+f"(d[3])
        : "r"(a0), "r"(a1), "r"(a2), "r"(a3), "r"(b0), "r"(b1));
}

// position of k (0..7) within the pair-packed group
DEV int kpos8(int k) { return ((k & 3) << 1) | ((k >> 2) & 1); }

// ================= weight tf32-convert + fragment-pack pre-kernel =================
__global__ void conv_w(const float* __restrict__ W1, const float* __restrict__ W2,
                       const float* __restrict__ W3)
{
    int idx = blockIdx.x * blockDim.x + threadIdx.x;
    int stride = gridDim.x * blockDim.x;
    for (int i = idx; i < 512 * 256; i += stride) {
        int k = i >> 8, n = i & 255;
        g_w1[(((k >> 3) * 256 + n) << 3) + kpos8(k & 7)] = f2tf(W1[i]);
    }
    for (int i = idx; i < 256 * 256; i += stride) {
        int k = i >> 8, n = i & 255;
        g_w2[(((k >> 3) * 256 + n) << 3) + kpos8(k & 7)] = f2tf(W2[i]);
    }
    for (int i = idx; i < 256 * 128; i += stride) {
        int k = i >> 7, n = i & 127;
        g_w3[(((k >> 3) * 128 + n) << 3) + kpos8(k & 7)] = f2tf(W3[i]);
    }
}

// ================= geometry =================
constexpr int BATCH = 16384;
constexpr int BT    = 8;
constexpr int MT    = 96;
constexpr int THREADS = 512;

constexpr int AFSTR = 260;   // A plane row stride (u32 words); 260 % 32 == 4 -> conflict-free LDS.32
constexpr int ASSTR = 36;    // layer-1 A slice row stride (32 k + pad); 36 % 32 == 4

// smem layout (bytes)
constexpr int A_OFF  = 0;                        // 96*260*4 = 99840 (tf32 activations, linear k)
constexpr int AS_SZ  = MT * ASSTR * 4;           // 13824; layer-1 slices alias A region
constexpr int HC_OFF = 99840;                    // fp32 scratch 96*264*4 = 101376
constexpr int HCSTR  = 264;                      // conflict-free D-store / mix reads
constexpr int AM_OFF = 201216;                   // 144 floats
constexpr int SMEM_BYTES = 201856;

// Fixed ECG graph neighbor lists (incl. self), 42 nonzeros of the 12x12 A_norm.
__device__ constexpr int NBR_OFF[13] = {0,5,11,16,20,23,26,28,31,34,37,40,42};
__device__ constexpr int NBR[42] = {
    0,1,2,3,4,
    0,1,2,3,4,5,
    0,1,2,3,5,
    0,1,2,3,
    0,1,4,
    1,2,5,
    6,7,
    6,7,8,
    7,8,9,
    8,9,10,
    9,10,11,
    10,11
};

// Load one kstep of B fragments into registers (NT LDG.64).
template<int NT>
DEV void load_bk(const u32* bp, u64* bv) {
    #pragma unroll
    for (int nt = 0; nt < NT; nt++)
        bv[nt] = *(const u64*)(bp + (nt << 6));
}

// One 8-k step of the tf32 GEMM with pre-loaded B registers.
// A: [96][astr] u32 (tf32 bits, linear k) in smem (LDS.32 fragments).
template<int NT>
DEV void gemm_compute(const u32* A, int astr, int kcol, int rb,
                      const u64* bv, float acc[3][NT][4], int lane)
{
    const int lr = lane >> 2;
    const int q  = lane & 3;
    #pragma unroll
    for (int mt = 0; mt < 3; mt++) {
        int r = rb + mt * 16 + lr;
        u32 a0 = A[r * astr + kcol + q];
        u32 a1 = A[(r + 8) * astr + kcol + q];
        u32 a2 = A[r * astr + kcol + q + 4];
        u32 a3 = A[(r + 8) * astr + kcol + q + 4];
        #pragma unroll
        for (int nt = 0; nt < NT; nt++)
            mma16808(acc[mt][nt], a0, a1, a2, a3, (u32)bv[nt], (u32)(bv[nt] >> 32));
    }
}

// Single-pass readback: all warps dump D into Hc, one sync, then all threads mix
// (A-mix + bias(+relu)) and write next-layer tf32 A plane, or fused mean/max epilogue.
template<int NT, bool FINAL>
DEV void readback(unsigned char* smem, float acc[3][NT][4],
                  const float* Am, const float* __restrict__ bias,
                  float* __restrict__ out, long long obase,
                  int tid, int lane, int rg, int cbase)
{
    float* Hc = (float*)(smem + HC_OFF);
    u32* afp = (u32*)(smem + A_OFF);
    const int lr = lane >> 2, q = lane & 3;
    #pragma unroll
    for (int mt = 0; mt < 3; mt++) {
        int r = rg * 48 + mt * 16 + lr;
        #pragma unroll
        for (int nt = 0; nt < NT; nt++) {
            int c = cbase + nt * 8 + q * 2;
            *(float2*)(Hc + r * HCSTR + c) = make_float2(acc[mt][nt][0], acc[mt][nt][1]);
            *(float2*)(Hc + (r + 8) * HCSTR + c) = make_float2(acc[mt][nt][2], acc[mt][nt][3]);
        }
    }
    __syncthreads();
    if (!FINAL) {
        #pragma unroll
        for (int s = 0; s < 4; s++) {
            int col = tid & 255;
            int b   = (tid >> 8) + 2 * s;
            float h[12];
            #pragma unroll
            for (int l = 0; l < 12; l++) h[l] = Hc[(b * 12 + l) * HCSTR + col];
            float bv = __ldg(bias + col);
            #pragma unroll
            for (int l = 0; l < 12; l++) {
                float a = 0.f;
                #pragma unroll
                for (int qq = NBR_OFF[l]; qq < NBR_OFF[l + 1]; qq++)
                    a += Am[l * 12 + NBR[qq]] * h[NBR[qq]];
                float y = fmaxf(a + bv, 0.f);
                afp[(b * 12 + l) * AFSTR + col] = f2tf(y);
            }
        }
        __syncthreads();
    } else {
        #pragma unroll
        for (int s = 0; s < 2; s++) {
            int col = tid & 127;
            int b   = (tid >> 7) + 4 * s;
            float h[12];
            #pragma unroll
            for (int l = 0; l < 12; l++) h[l] = Hc[(b * 12 + l) * HCSTR + col];
            float bv = __ldg(bias + col);
            float sum = 0.f, mx = -3.402823466e38f;
            #pragma unroll
            for (int l = 0; l < 12; l++) {
                float a = 0.f;
                #pragma unroll
                for (int qq = NBR_OFF[l]; qq < NBR_OFF[l + 1]; qq++)
                    a += Am[l * 12 + NBR[qq]] * h[NBR[qq]];
                float y = a + bv;
                sum += y;
                mx = fmaxf(mx, y);
            }
            float* op = out + (obase + b) * 256;
            op[col]       = sum * (1.0f / 12.0f);
            op[128 + col] = mx;
        }
    }
}

__global__ void __launch_bounds__(THREADS, 1)
ecg_mma(const float* __restrict__ x,
        const float* __restrict__ b1, const float* __restrict__ b2,
        const float* __restrict__ b3, float* __restrict__ out)
{
    extern __shared__ unsigned char smem[];
    float* Am = (float*)(smem + AM_OFF);

    const int tid  = threadIdx.x;
    const int lane = tid & 31;
    const int w    = tid >> 5;       // 0..15
    const int rg   = w >> 3;         // 0..1 (M group)
    const int cg   = w & 7;          // 0..7 (N group)
    const int rb   = rg * 48;
    const int cb   = cg * 32;        // N=256 layers
    const int cb3  = cg * 16;        // N=128 layer
    const int lr   = lane >> 2;
    const int q    = lane & 3;
    const long long rowbase = (long long)blockIdx.x * MT;
    const long long obase   = (long long)blockIdx.x * BT;

    if (tid == 0) {
        float a[12][12];
        for (int i = 0; i < 12; i++)
            for (int j = 0; j < 12; j++) a[i][j] = (i == j) ? 2.0f : 0.0f;
        const int ei[15] = {0,0,1,0,1,2,0,1,1,2,6,7,8,9,10};
        const int ej[15] = {1,2,2,3,3,3,4,4,5,5,7,8,9,10,11};
        for (int e = 0; e < 15; e++) { a[ei[e]][ej[e]] = 1.0f; a[ej[e]][ei[e]] = 1.0f; }
        float dinv[12];
        for (int i = 0; i < 12; i++) {
            float s = 0.f;
            for (int j = 0; j < 12; j++) s += a[i][j];
            dinv[i] = 1.0f / sqrtf(s);
        }
        for (int i = 0; i < 12; i++)
            for (int j = 0; j < 12; j++)
                Am[i * 12 + j] = dinv[i] * a[i][j] * dinv[j];
    }

    // per-warp B fragment base offsets (u32 units): (cb + lr)*8 + 2q
    const u32* bp1 = g_w1 + ((cb  + lr) << 3) + (q << 1);
    const u32* bp2 = g_w2 + ((cb  + lr) << 3) + (q << 1);
    const u32* bp3 = g_w3 + ((cb3 + lr) << 3) + (q << 1);
    constexpr int KSTEP256 = 256 * 8;   // u32 per 8-k step, N=256
    constexpr int KSTEP128 = 128 * 8;   // N=128

    // layer-1 A staging: row xr (active <96), k-quarter xq (8 floats each)
    const int xr = tid >> 2, xq = tid & 3;
    const bool xact = tid < MT * 4;

    u32* as_[2] = {(u32*)(smem + A_OFF), (u32*)(smem + A_OFF + AS_SZ)};

    float acc[3][4][4];
    #pragma unroll
    for (int i = 0; i < 3; i++)
        #pragma unroll
        for (int j = 0; j < 4; j++)
            #pragma unroll
            for (int v = 0; v < 4; v++) acc[i][j][v] = 0.f;

    u64 B[4][4];   // rotating B register buffers (2 ksteps ahead)

    // ---------------- Layer 1: X(96x512) @ W1 (K=512, 16 slices of 32 k) ----------------
    {
        if (xact) {
            float4 v0 = *(const float4*)(x + (rowbase + xr) * 512 + xq * 8);
            float4 v1 = *(const float4*)(x + (rowbase + xr) * 512 + xq * 8 + 4);
            u32* d = as_[0] + xr * ASSTR + xq * 8;
            *(uint4*)(d)     = make_uint4(f2tf(v0.x), f2tf(v0.y), f2tf(v0.z), f2tf(v0.w));
            *(uint4*)(d + 4) = make_uint4(f2tf(v1.x), f2tf(v1.y), f2tf(v1.z), f2tf(v1.w));
        }
        load_bk<4>(bp1, B[0]);
        load_bk<4>(bp1 + KSTEP256, B[1]);
        __syncthreads();

        for (int it = 0; it < 16; it++) {
            const int cur = it & 1, nxt = cur ^ 1;
            const bool more = it < 15;
            float4 v0, v1;
            if (more && xact) {
                v0 = *(const float4*)(x + (rowbase + xr) * 512 + (it + 1) * 32 + xq * 8);
                v1 = *(const float4*)(x + (rowbase + xr) * 512 + (it + 1) * 32 + xq * 8 + 4);
            }
            #pragma unroll
            for (int ks = 0; ks < 4; ks++) {
                int j = it * 4 + ks;
                if (j + 2 < 64)
                    load_bk<4>(bp1 + (j + 2) * KSTEP256, B[(ks + 2) & 3]);
                gemm_compute<4>(as_[cur], ASSTR, ks * 8, rb, B[ks & 3], acc, lane);
            }
            if (more && xact) {
                u32* d = as_[nxt] + xr * ASSTR + xq * 8;
                *(uint4*)(d)     = make_uint4(f2tf(v0.x), f2tf(v0.y), f2tf(v0.z), f2tf(v0.w));
                *(uint4*)(d + 4) = make_uint4(f2tf(v1.x), f2tf(v1.y), f2tf(v1.z), f2tf(v1.w));
            }
            __syncthreads();
        }
    }
    readback<4, false>(smem, acc, Am, b1, out, obase, tid, lane, rg, cb);

    // ---------------- Layer 2: H1(96x256) @ W2 (K=256, 32 ksteps, NO barriers) ----------------
    #pragma unroll
    for (int i = 0; i < 3; i++)
        #pragma unroll
        for (int j = 0; j < 4; j++)
            #pragma unroll
            for (int v = 0; v < 4; v++) acc[i][j][v] = 0.f;
    {
        const u32* afp = (const u32*)(smem + A_OFF);
        load_bk<4>(bp2, B[0]);
        load_bk<4>(bp2 + KSTEP256, B[1]);
        #pragma unroll 4
        for (int kc = 0; kc < 32; kc++) {
            if (kc + 2 < 32)
                load_bk<4>(bp2 + (kc + 2) * KSTEP256, B[(kc + 2) & 3]);
            gemm_compute<4>(afp, AFSTR, kc * 8, rb, B[kc & 3], acc, lane);
        }
    }
    readback<4, false>(smem, acc, Am, b2, out, obase, tid, lane, rg, cb);

    // ---------------- Layer 3: H2(96x256) @ W3 (K=256, 32 ksteps, N=128, NO barriers) ----------------
    float acc3[3][2][4];
    #pragma unroll
    for (int i = 0; i < 3; i++)
        #pragma unroll
        for (int j = 0; j < 2; j++)
            #pragma unroll
            for (int v = 0; v < 4; v++) acc3[i][j][v] = 0.f;
    {
        const u32* afp = (const u32*)(smem + A_OFF);
        u64 B3[4][2];
        load_bk<2>(bp3, B3[0]);
        load_bk<2>(bp3 + KSTEP128, B3[1]);
        #pragma unroll 4
        for (int kc = 0; kc < 32; kc++) {
            if (kc + 2 < 32)
                load_bk<2>(bp3 + (kc + 2) * KSTEP128, B3[(kc + 2) & 3]);
            gemm_compute<2>(afp, AFSTR, kc * 8, rb, B3[kc & 3], acc3, lane);
        }
    }
    readback<2, true>(smem, acc3, Am, b3, out, obase, tid, lane, rg, cb3);
}

extern "C" void kernel_launch(void* const* d_in, const int* in_sizes, int n_in,
                              void* d_out, int out_size)
{
    const float* x  = (const float*)d_in[0];
    const float* W1 = (const float*)d_in[1];
    const float* b1 = (const float*)d_in[2];
    const float* W2 = (const float*)d_in[3];
    const float* b2 = (const float*)d_in[4];
    const float* W3 = (const float*)d_in[5];
    const float* b3 = (const float*)d_in[6];
    float* out = (float*)d_out;

    conv_w<<<148, 512>>>(W1, W2, W3);

    cudaFuncSetAttribute(ecg_mma, cudaFuncAttributeMaxDynamicSharedMemorySize, SMEM_BYTES);
    ecg_mma<<<BATCH / BT, THREADS, SMEM_BYTES>>>(x, b1, b2, b3, out);
}